// round 8
// baseline (speedup 1.0000x reference)
#include <cuda_runtime.h>
#include <cuda_bf16.h>

// Problem constants
#define Bz 4
#define Nz 128
#define Mz 128
#define Dz 256
#define BDz 1024

#define KSPLIT 4
#define TSZ (Bz * Nz * Dz)      // 131072 elems (T)
#define SSZ (Bz * Nz * Mz)      // 65536 elems (S)

#define N_K2 128                // k2 consumer blocks (bids [0,128))
#define N_K3 64                 // k3 consumer blocks (bids [128,192))
#define PROD_BASE (N_K2 + N_K3) // 192: first producer bid
#define N_PROD 8192             // k1 producer blocks
#define GRID_TOT (PROD_BASE + N_PROD)

// Scratch in device globals (no allocation allowed). Zero-initialized at load;
// sync counters are restored to zero by the last epilogue block each launch,
// so graph replays are deterministic.
__device__ float g_Aw[Dz * Dz];            // Aw[d][e] = sum_k A[d,e,k]*W[k]
__device__ float g_Tp[KSPLIT * TSZ];       // T partials, split over d-chunks
__device__ float g_Sp[KSPLIT * SSZ];       // S partials, split over e-chunks
__device__ int   g_doneA[4];               // producers done per d-chunk (target 2048)
__device__ int   g_flag2[8 * 4 * 4];       // k2 tile done: [rtile][etile][ksd]
__device__ int   g_cnt3[16];               // k3 split-K epilogue tickets
__device__ int   g_epi;                    // epilogue winners (target 16 -> reset)

__device__ __forceinline__ int ld_vol(const int* p) { return *(volatile const int*)p; }

// ---------------------------------------------------------------------------
// Mega-kernel: k1 (8192 producer blocks) + k2 (128) + k3+epilogue (64),
// one launch. Consumers hold the lowest bids -> resident from wave 1,
// overlap with k1 via per-chunk counters/flags.
// ---------------------------------------------------------------------------
__global__ __launch_bounds__(256) void k_mega(const float* __restrict__ A,
                                              const float* __restrict__ W,
                                              const float* __restrict__ X,
                                              const float* __restrict__ Y,
                                              const float* __restrict__ bias,
                                              float* __restrict__ S) {
    __shared__ __align__(16) float sBufA[64 * 65];   // 16.6 KB
    __shared__ __align__(16) float sBufB[64 * 65];   // 16.6 KB
    __shared__ int sLast;

    int tid = threadIdx.x;
    int bid = blockIdx.x;

    if (bid >= PROD_BASE) {
        // ================= k1 producer (exact round-2 body) =================
        int pb = bid - PROD_BASE;                    // [0, 8192)
        float4* sW = reinterpret_cast<float4*>(sBufA);
        sW[tid] = reinterpret_cast<const float4*>(W)[tid];
        __syncthreads();

        int warp = tid >> 5;
        int lane = tid & 31;
        long row = (long)pb * 8 + warp;              // [0, 65536)
        const float4* Arow = reinterpret_cast<const float4*>(A) + row * (BDz / 4);

        float acc = 0.0f;
#pragma unroll
        for (int i = 0; i < 8; i++) {
            float4 a = Arow[i * 32 + lane];
            float4 w = sW[i * 32 + lane];
            acc += a.x * w.x + a.y * w.y + a.z * w.z + a.w * w.w;
        }
#pragma unroll
        for (int off = 16; off; off >>= 1)
            acc += __shfl_xor_sync(0xffffffffu, acc, off);
        if (lane == 0) g_Aw[row] = acc;

        __threadfence();
        __syncthreads();
        if (tid == 0) atomicAdd(&g_doneA[pb >> 11], 1);   // d-chunk = pb/2048
        return;
    }

    int tx = tid & 15;
    int ty = tid >> 4;

    if (bid < N_K2) {
        // ================= k2 consumer: Tp[ksd] tile ========================
        int ksd   = bid & 3;
        int rtile = (bid >> 2) & 7;
        int etile = bid >> 5;            // 0..3
        int e0 = etile * 64;
        int r0 = rtile * 64;
        int kc = ksd * 64;

        float (*sX)[65] = reinterpret_cast<float(*)[65]>(sBufA);
        float (*sA)[65] = reinterpret_cast<float(*)[65]>(sBufB);

        // X is input-ready: load while waiting
#pragma unroll
        for (int t = 0; t < 4; t++) {
            int lin = tid + t * 256;
            int row = lin >> 4;
            int c4  = (lin & 15) << 2;
            float4 xv = *reinterpret_cast<const float4*>(&X[(r0 + row) * Dz + kc + c4]);
            sX[row][c4 + 0] = xv.x; sX[row][c4 + 1] = xv.y;
            sX[row][c4 + 2] = xv.z; sX[row][c4 + 3] = xv.w;
        }

        if (tid == 0) {
            while (ld_vol(&g_doneA[ksd]) < 2048) __nanosleep(128);
            __threadfence();
        }
        __syncthreads();

#pragma unroll
        for (int t = 0; t < 4; t++) {
            int lin = tid + t * 256;
            int row = lin >> 4;
            int c4  = (lin & 15) << 2;
            float4 av = *reinterpret_cast<const float4*>(&g_Aw[(kc + row) * Dz + e0 + c4]);
            sA[row][c4 + 0] = av.x; sA[row][c4 + 1] = av.y;
            sA[row][c4 + 2] = av.z; sA[row][c4 + 3] = av.w;
        }
        __syncthreads();

        float acc[4][4] = {};
#pragma unroll 16
        for (int k = 0; k < 64; k++) {
            float xv[4], av[4];
#pragma unroll
            for (int i = 0; i < 4; i++) xv[i] = sX[ty + 16 * i][k];
#pragma unroll
            for (int j = 0; j < 4; j++) av[j] = sA[k][tx + 16 * j];
#pragma unroll
            for (int i = 0; i < 4; i++)
#pragma unroll
                for (int j = 0; j < 4; j++)
                    acc[i][j] += xv[i] * av[j];
        }

        float* out = g_Tp + (long)ksd * TSZ;
#pragma unroll
        for (int i = 0; i < 4; i++)
#pragma unroll
            for (int j = 0; j < 4; j++)
                out[(r0 + ty + 16 * i) * Dz + e0 + tx + 16 * j] = acc[i][j];

        __threadfence();
        __syncthreads();
        if (tid == 0) atomicExch(&g_flag2[(rtile * 4 + etile) * 4 + ksd], 1);
        return;
    }

    // ================= k3 consumer: S tile split over e-chunks ==============
    {
        int idx = bid - N_K2;            // 0..63
        int mt  = idx & 1;
        int nt  = (idx >> 1) & 1;
        int z   = idx >> 2;              // 0..15
        int b   = z >> 2;
        int kse = z & 3;
        int m0 = mt * 64;
        int n0 = nt * 64;
        int kc = kse * 64;               // e chunk
        int rtile = b * 2 + nt;
        int gid = (b * 2 + nt) * 2 + mt; // 0..15

        float (*sT)[65] = reinterpret_cast<float(*)[65]>(sBufA);
        float (*sY)[65] = reinterpret_cast<float(*)[65]>(sBufB);

        long tb = (long)b * Nz * Dz;
        const float* Yb = Y + (long)b * Mz * Dz;

        // Y is input-ready: load first
#pragma unroll
        for (int t = 0; t < 4; t++) {
            int lin = tid + t * 256;
            int row = lin >> 4;
            int c4  = (lin & 15) << 2;
            float4 yv = *reinterpret_cast<const float4*>(&Yb[(long)(m0 + row) * Dz + kc + c4]);
            sY[row][c4 + 0] = yv.x; sY[row][c4 + 1] = yv.y;
            sY[row][c4 + 2] = yv.z; sY[row][c4 + 3] = yv.w;
        }

        // Accumulate T chunk-by-chunk as k2 tiles complete (0..2 arrive
        // during k1; only chunk 3 is on the critical path).
        for (int ksd = 0; ksd < KSPLIT; ksd++) {
            if (tid == 0) {
                while (ld_vol(&g_flag2[(rtile * 4 + kse) * 4 + ksd]) == 0) __nanosleep(128);
                __threadfence();
            }
            __syncthreads();
            const float* tp = g_Tp + (long)ksd * TSZ;
#pragma unroll
            for (int t = 0; t < 4; t++) {
                int lin = tid + t * 256;
                int row = lin >> 4;
                int c4  = (lin & 15) << 2;
                long base = tb + (long)(n0 + row) * Dz + kc + c4;
                float4 tv = *reinterpret_cast<const float4*>(&tp[base]);
                if (ksd == 0) {
                    sT[row][c4 + 0] = tv.x; sT[row][c4 + 1] = tv.y;
                    sT[row][c4 + 2] = tv.z; sT[row][c4 + 3] = tv.w;
                } else {
                    sT[row][c4 + 0] += tv.x; sT[row][c4 + 1] += tv.y;
                    sT[row][c4 + 2] += tv.z; sT[row][c4 + 3] += tv.w;
                }
            }
        }
        __syncthreads();

        float acc[4][4] = {};
#pragma unroll 16
        for (int e = 0; e < 64; e++) {
            float tv[4], yv[4];
#pragma unroll
            for (int i = 0; i < 4; i++) tv[i] = sT[ty + 16 * i][e];
#pragma unroll
            for (int j = 0; j < 4; j++) yv[j] = sY[tx + 16 * j][e];
#pragma unroll
            for (int i = 0; i < 4; i++)
#pragma unroll
                for (int j = 0; j < 4; j++)
                    acc[i][j] += tv[i] * yv[j];
        }

        long sbase = (long)b * Nz * Mz;
        float* out = g_Sp + (long)kse * SSZ + sbase;
#pragma unroll
        for (int i = 0; i < 4; i++)
#pragma unroll
            for (int j = 0; j < 4; j++)
                out[(n0 + ty + 16 * i) * Mz + m0 + tx + 16 * j] = acc[i][j];

        __threadfence();
        __syncthreads();
        if (tid == 0) sLast = (atomicAdd(&g_cnt3[gid], 1) == KSPLIT - 1);
        __syncthreads();

        if (sLast) {
            float bv = bias[0];
#pragma unroll
            for (int t = 0; t < 4; t++) {
                int lin = tid + t * 256;
                int row = lin >> 4;
                int c4  = (lin & 15) << 2;
                long p = sbase + (long)(n0 + row) * Mz + m0 + c4;
                float4 a0 = *reinterpret_cast<const float4*>(&g_Sp[0 * SSZ + p]);
                float4 a1 = *reinterpret_cast<const float4*>(&g_Sp[1 * SSZ + p]);
                float4 a2 = *reinterpret_cast<const float4*>(&g_Sp[2 * SSZ + p]);
                float4 a3 = *reinterpret_cast<const float4*>(&g_Sp[3 * SSZ + p]);
                float4 r;
                r.x = a0.x + a1.x + a2.x + a3.x + bv;
                r.y = a0.y + a1.y + a2.y + a3.y + bv;
                r.z = a0.z + a1.z + a2.z + a3.z + bv;
                r.w = a0.w + a1.w + a2.w + a3.w + bv;
                *reinterpret_cast<float4*>(&S[p]) = r;
            }
            __threadfence();
            if (tid == 0) {
                int w = atomicAdd(&g_epi, 1);
                if (w == 15) {
                    // Last epilogue on the chip: restore counters for replay.
#pragma unroll
                    for (int i = 0; i < 4; i++)  g_doneA[i] = 0;
                    for (int i = 0; i < 128; i++) g_flag2[i] = 0;
#pragma unroll
                    for (int i = 0; i < 16; i++) g_cnt3[i] = 0;
                    g_epi = 0;
                }
            }
        }
    }
}

// ---------------------------------------------------------------------------
// Launch: inputs in order X, Y, A, W, b  — single kernel launch.
// ---------------------------------------------------------------------------
extern "C" void kernel_launch(void* const* d_in, const int* in_sizes, int n_in,
                              void* d_out, int out_size) {
    const float* X = (const float*)d_in[0];  // [4,128,256]
    const float* Y = (const float*)d_in[1];  // [4,128,256]
    const float* A = (const float*)d_in[2];  // [256,256,1024]
    const float* W = (const float*)d_in[3];  // [1,1024]
    const float* b = (const float*)d_in[4];  // [1]
    float* S = (float*)d_out;                // [4,128,128]

    k_mega<<<GRID_TOT, 256>>>(A, W, X, Y, b, S);
}

// round 9
// speedup vs baseline: 1.1866x; 1.1866x over previous
#include <cuda_runtime.h>
#include <cuda_bf16.h>

// Problem constants
#define Bz 4
#define Nz 128
#define Mz 128
#define Dz 256
#define BDz 1024

#define KSPLIT 4
#define TSZ (Bz * Nz * Dz)      // 131072 elems (T)
#define SSZ (Bz * Nz * Mz)      // 65536 elems (S)

// Scratch in device globals (no allocation allowed).
__device__ float g_Aw[Dz * Dz];            // Aw[d][e] = sum_k A[d,e,k]*W[k]
__device__ float g_Tp[KSPLIT * TSZ];       // T partials, split over d-chunks
__device__ float g_Sp[KSPLIT * SSZ];       // S partials, split over e-chunks
__device__ int   g_bar;                    // grid barrier for ktail (reset by k1)

__device__ __forceinline__ int ld_vol(const int* p) { return *(volatile const int*)p; }

// ---------------------------------------------------------------------------
// Kernel 1 (round-2 proven body, FROZEN): Aw[row] = dot(A[row,:1024], W).
// One warp per row; W in smem; float4 loads. 268 MB streamed at ~6.55 TB/s.
// Block 0 resets ktail's barrier counter (stream order => replay-safe).
// ---------------------------------------------------------------------------
__global__ __launch_bounds__(256) void k1_reduce_A(const float* __restrict__ A,
                                                   const float* __restrict__ W) {
    __shared__ float4 sW[BDz / 4];
    int tid = threadIdx.x;
    if (blockIdx.x == 0 && tid == 0) g_bar = 0;
    sW[tid] = reinterpret_cast<const float4*>(W)[tid];
    __syncthreads();

    int warp = tid >> 5;
    int lane = tid & 31;
    long row = (long)blockIdx.x * 8 + warp;
    const float4* Arow = reinterpret_cast<const float4*>(A) + row * (BDz / 4);

    float acc = 0.0f;
#pragma unroll
    for (int i = 0; i < 8; i++) {
        float4 a = Arow[i * 32 + lane];
        float4 w = sW[i * 32 + lane];
        acc += a.x * w.x + a.y * w.y + a.z * w.z + a.w * w.w;
    }
#pragma unroll
    for (int off = 16; off; off >>= 1)
        acc += __shfl_xor_sync(0xffffffffu, acc, off);
    if (lane == 0) g_Aw[row] = acc;
}

// ---------------------------------------------------------------------------
// Tail kernel: 128 blocks (<= 148 SMs => all co-resident in wave 1, so the
// spin barrier is deadlock-free). Three phases, two grid barriers:
//   A: 128 k2 split tiles:  Tp[ksd][r,e] = sum_{d chunk} X[r,d]*Aw[d,e]
//   B: 128 k3 tiles (32n x 64m, e-chunk 64): Sp[kse] = Tsum @ Y^T
//   C: S = sum_kse Sp + bias  (1 float4 per thread)
// All FP reductions in fixed index order => deterministic.
// ---------------------------------------------------------------------------
__global__ __launch_bounds__(256) void ktail(const float* __restrict__ X,
                                             const float* __restrict__ Y,
                                             const float* __restrict__ bias,
                                             float* __restrict__ S) {
    __shared__ __align__(16) float sA[64][65];
    __shared__ __align__(16) float sB[64][65];

    int tid = threadIdx.x;
    int bid = blockIdx.x;
    int tx = tid & 15;
    int ty = tid >> 4;

    // ===================== Phase A: k2 split tile =====================
    {
        int ksd   = bid & 3;
        int rtile = (bid >> 2) & 7;
        int etile = bid >> 5;            // 0..3
        int e0 = etile * 64;
        int r0 = rtile * 64;
        int kc = ksd * 64;

#pragma unroll
        for (int t = 0; t < 4; t++) {
            int lin = tid + t * 256;
            int row = lin >> 4;
            int c4  = (lin & 15) << 2;
            float4 xv = *reinterpret_cast<const float4*>(&X[(r0 + row) * Dz + kc + c4]);
            sA[row][c4 + 0] = xv.x; sA[row][c4 + 1] = xv.y;
            sA[row][c4 + 2] = xv.z; sA[row][c4 + 3] = xv.w;
            float4 av = *reinterpret_cast<const float4*>(&g_Aw[(kc + row) * Dz + e0 + c4]);
            sB[row][c4 + 0] = av.x; sB[row][c4 + 1] = av.y;
            sB[row][c4 + 2] = av.z; sB[row][c4 + 3] = av.w;
        }
        __syncthreads();

        float acc[4][4] = {};
#pragma unroll 16
        for (int k = 0; k < 64; k++) {
            float xv[4], av[4];
#pragma unroll
            for (int i = 0; i < 4; i++) xv[i] = sA[ty + 16 * i][k];
#pragma unroll
            for (int j = 0; j < 4; j++) av[j] = sB[k][tx + 16 * j];
#pragma unroll
            for (int i = 0; i < 4; i++)
#pragma unroll
                for (int j = 0; j < 4; j++)
                    acc[i][j] += xv[i] * av[j];
        }

        float* out = g_Tp + (long)ksd * TSZ;
#pragma unroll
        for (int i = 0; i < 4; i++)
#pragma unroll
            for (int j = 0; j < 4; j++)
                out[(r0 + ty + 16 * i) * Dz + e0 + tx + 16 * j] = acc[i][j];
    }

    // ---- grid barrier 1 ----
    __threadfence();
    __syncthreads();
    if (tid == 0) {
        atomicAdd(&g_bar, 1);
        while (ld_vol(&g_bar) < 128) __nanosleep(64);
        __threadfence();
    }
    __syncthreads();

    // ===================== Phase B: k3 tile (32n x 64m) =====================
    {
        int mt = bid & 1;                // m-tile of 64
        int nt = (bid >> 1) & 3;         // n-tile of 32
        int z  = bid >> 3;               // 0..15
        int b  = z >> 2;
        int kse = z & 3;
        int m0 = mt * 64;
        int n0 = nt * 32;
        int kc = kse * 64;

        float (*sT)[65] = sA;            // 32 rows used
        float (*sY)[65] = sB;            // 64 rows

        long tb = (long)b * Nz * Dz;
        const float* Yb = Y + (long)b * Mz * Dz;

        // sT: 32x64 = 512 float4 slots across 512 lins
#pragma unroll
        for (int t = 0; t < 2; t++) {
            int lin = tid + t * 256;     // 0..511
            int row = lin >> 4;          // 0..31
            int c4  = (lin & 15) << 2;
            long base = tb + (long)(n0 + row) * Dz + kc + c4;
            float4 t0 = *reinterpret_cast<const float4*>(&g_Tp[0 * TSZ + base]);
            float4 t1 = *reinterpret_cast<const float4*>(&g_Tp[1 * TSZ + base]);
            float4 t2 = *reinterpret_cast<const float4*>(&g_Tp[2 * TSZ + base]);
            float4 t3 = *reinterpret_cast<const float4*>(&g_Tp[3 * TSZ + base]);
            sT[row][c4 + 0] = t0.x + t1.x + t2.x + t3.x;
            sT[row][c4 + 1] = t0.y + t1.y + t2.y + t3.y;
            sT[row][c4 + 2] = t0.z + t1.z + t2.z + t3.z;
            sT[row][c4 + 3] = t0.w + t1.w + t2.w + t3.w;
        }
        // sY: 64x64 = 1024 float4 slots
#pragma unroll
        for (int t = 0; t < 4; t++) {
            int lin = tid + t * 256;
            int row = lin >> 4;
            int c4  = (lin & 15) << 2;
            float4 yv = *reinterpret_cast<const float4*>(&Yb[(long)(m0 + row) * Dz + kc + c4]);
            sY[row][c4 + 0] = yv.x; sY[row][c4 + 1] = yv.y;
            sY[row][c4 + 2] = yv.z; sY[row][c4 + 3] = yv.w;
        }
        __syncthreads();

        float acc[2][4] = {};
#pragma unroll 16
        for (int e = 0; e < 64; e++) {
            float tv[2], yv[4];
#pragma unroll
            for (int i = 0; i < 2; i++) tv[i] = sT[ty + 16 * i][e];
#pragma unroll
            for (int j = 0; j < 4; j++) yv[j] = sY[tx + 16 * j][e];
#pragma unroll
            for (int i = 0; i < 2; i++)
#pragma unroll
                for (int j = 0; j < 4; j++)
                    acc[i][j] += tv[i] * yv[j];
        }

        float* out = g_Sp + (long)kse * SSZ + (long)b * Nz * Mz;
#pragma unroll
        for (int i = 0; i < 2; i++)
#pragma unroll
            for (int j = 0; j < 4; j++)
                out[(n0 + ty + 16 * i) * Mz + m0 + tx + 16 * j] = acc[i][j];
    }

    // ---- grid barrier 2 ----
    __threadfence();
    __syncthreads();
    if (tid == 0) {
        atomicAdd(&g_bar, 1);
        while (ld_vol(&g_bar) < 256) __nanosleep(64);
        __threadfence();
    }
    __syncthreads();

    // ===================== Phase C: reduce Sp + bias -> S ===================
    if (tid < 128) {
        int idx = bid * 128 + tid;               // 0..16383 float4 slots
        float bv = bias[0];
        const float4* p0 = reinterpret_cast<const float4*>(g_Sp + 0 * SSZ);
        const float4* p1 = reinterpret_cast<const float4*>(g_Sp + 1 * SSZ);
        const float4* p2 = reinterpret_cast<const float4*>(g_Sp + 2 * SSZ);
        const float4* p3 = reinterpret_cast<const float4*>(g_Sp + 3 * SSZ);
        float4 a = p0[idx], b2 = p1[idx], c = p2[idx], d = p3[idx];
        float4 r;
        r.x = a.x + b2.x + c.x + d.x + bv;
        r.y = a.y + b2.y + c.y + d.y + bv;
        r.z = a.z + b2.z + c.z + d.z + bv;
        r.w = a.w + b2.w + c.w + d.w + bv;
        reinterpret_cast<float4*>(S)[idx] = r;
    }
}

// ---------------------------------------------------------------------------
// Launch: inputs in order X, Y, A, W, b — two launches total.
// ---------------------------------------------------------------------------
extern "C" void kernel_launch(void* const* d_in, const int* in_sizes, int n_in,
                              void* d_out, int out_size) {
    const float* X = (const float*)d_in[0];  // [4,128,256]
    const float* Y = (const float*)d_in[1];  // [4,128,256]
    const float* A = (const float*)d_in[2];  // [256,256,1024]
    const float* W = (const float*)d_in[3];  // [1,1024]
    const float* b = (const float*)d_in[4];  // [1]
    float* S = (float*)d_out;                // [4,128,128]

    k1_reduce_A<<<8192, 256>>>(A, W);
    ktail<<<128, 256>>>(X, Y, b, S);
}